// round 1
// baseline (speedup 1.0000x reference)
#include <cuda_runtime.h>

#define NB 4
#define NN 2048
#define NC 768
#define NH 12
#define ND 64

// ---------------- scratch (device globals; no allocation allowed) ----------
__device__ float g_q[NB * NH * NN * ND];   // [B,H,N,D]
__device__ float g_k[NB * NH * NN * ND];
__device__ float g_v[NB * NH * NN * ND];
__device__ float g_ao[NB * NN * NC];       // attention output, [B,N,C]
__device__ float g_t[NB * NN * NC];        // out-proj result, [B*N, C]

// ---------------------------------------------------------------------------
// Fused QKV projection GEMM: dst = A @ W^T + bias
// A: [8192, 768] row-major, W: [768, 768] row-major (row n over k).
// blockIdx.z selects q/k/v. Tile 64x64, BK=16, 256 threads, 4x4 micro-tile.
// Output written directly in [B,H,N,D] layout (n-tile == head since D=64).
// ---------------------------------------------------------------------------
__global__ __launch_bounds__(256) void qkv_gemm(
    const float* __restrict__ x1, const float* __restrict__ x2,
    const float* __restrict__ Wq, const float* __restrict__ bq,
    const float* __restrict__ Wk, const float* __restrict__ bk,
    const float* __restrict__ Wv, const float* __restrict__ bv)
{
    const int z = blockIdx.z;
    const float* A    = (z == 0) ? x1 : x2;
    const float* W    = (z == 0) ? Wq : (z == 1) ? Wk : Wv;
    const float* bias = (z == 0) ? bq : (z == 1) ? bk : bv;
    float* dst        = (z == 0) ? g_q : (z == 1) ? g_k : g_v;

    const int h  = blockIdx.x;        // n-tile == head (64 cols per head)
    const int m0 = blockIdx.y * 64;
    const int tid = threadIdx.x;
    const int tx = tid & 15;
    const int ty = tid >> 4;

    __shared__ float As[16 * 68];     // k-major: As[kk][m]
    __shared__ float Ws[16 * 68];     // k-major: Ws[kk][n]

    float acc[4][4];
#pragma unroll
    for (int i = 0; i < 4; i++)
#pragma unroll
        for (int j = 0; j < 4; j++) acc[i][j] = 0.f;

    const int lrow = tid >> 2;        // 0..63
    const int lk4  = (tid & 3) << 2;  // 0,4,8,12

    const float* arow = A + (size_t)(m0 + lrow) * NC + lk4;
    const float* wrow = W + (size_t)(h * 64 + lrow) * NC + lk4;

    for (int k0 = 0; k0 < NC; k0 += 16) {
        float4 fa = *(const float4*)(arow + k0);
        float4 fw = *(const float4*)(wrow + k0);
        __syncthreads();
        As[(lk4 + 0) * 68 + lrow] = fa.x;
        As[(lk4 + 1) * 68 + lrow] = fa.y;
        As[(lk4 + 2) * 68 + lrow] = fa.z;
        As[(lk4 + 3) * 68 + lrow] = fa.w;
        Ws[(lk4 + 0) * 68 + lrow] = fw.x;
        Ws[(lk4 + 1) * 68 + lrow] = fw.y;
        Ws[(lk4 + 2) * 68 + lrow] = fw.z;
        Ws[(lk4 + 3) * 68 + lrow] = fw.w;
        __syncthreads();
#pragma unroll
        for (int kk = 0; kk < 16; kk++) {
            float a[4], b[4];
            *(float4*)a = *(const float4*)(As + kk * 68 + ty * 4);
            *(float4*)b = *(const float4*)(Ws + kk * 68 + tx * 4);
#pragma unroll
            for (int i = 0; i < 4; i++)
#pragma unroll
                for (int j = 0; j < 4; j++) acc[i][j] += a[i] * b[j];
        }
    }

    float bb[4];
#pragma unroll
    for (int j = 0; j < 4; j++) bb[j] = bias[h * 64 + tx * 4 + j];

    const int b     = m0 / NN;        // 64 | 2048, so tile is in one batch
    const int nbase = m0 % NN;
#pragma unroll
    for (int i = 0; i < 4; i++) {
        int n = nbase + ty * 4 + i;
        float4 o;
        o.x = acc[i][0] + bb[0];
        o.y = acc[i][1] + bb[1];
        o.z = acc[i][2] + bb[2];
        o.w = acc[i][3] + bb[3];
        *(float4*)(dst + (((size_t)(b * NH + h)) * NN + n) * ND + tx * 4) = o;
    }
}

// ---------------------------------------------------------------------------
// Flash attention: one block per (m-tile of 64 rows, b*h). Online softmax.
// smem tiles stored k-major so fragment loads are LDS.128.
// ---------------------------------------------------------------------------
#define FPAD 68
__global__ __launch_bounds__(256) void flash_kernel(
    const float* __restrict__ mask1, const float* __restrict__ mask2,
    const float* __restrict__ temp_p)
{
    const int mt = blockIdx.x;        // 0..31
    const int bh = blockIdx.y;        // 0..47
    const int b  = bh / NH;
    const int h  = bh % NH;
    const int tid = threadIdx.x;
    const int tx = tid & 15;
    const int ty = tid >> 4;

    extern __shared__ float sm[];
    float* Qs = sm;                   // [kk][r]  (64 x 68)
    float* Ks = Qs + 64 * FPAD;       // [kk][c]
    float* Vs = Ks + 64 * FPAD;       // [c][d]
    float* Ps = Vs + 64 * FPAD;       // [c][r]

    const float inv_temp = 1.0f / temp_p[0];
    const float scale = 0.125f;       // 1/sqrt(64)

    const float* qbase = g_q + ((size_t)bh * NN + mt * 64) * ND;
    const float* kbase = g_k + (size_t)bh * NN * ND;
    const float* vbase = g_v + (size_t)bh * NN * ND;

    // load Q tile transposed (once)
#pragma unroll
    for (int i = 0; i < 4; i++) {
        int idx = tid + i * 256;      // float4 index 0..1023
        int r   = idx >> 4;
        int c4  = (idx & 15) << 2;
        float4 f = *(const float4*)(qbase + r * 64 + c4);
        Qs[(c4 + 0) * FPAD + r] = f.x;
        Qs[(c4 + 1) * FPAD + r] = f.y;
        Qs[(c4 + 2) * FPAD + r] = f.z;
        Qs[(c4 + 3) * FPAD + r] = f.w;
    }

    float m1r[4];
    const float* m1 = mask1 + b * NN + mt * 64;
#pragma unroll
    for (int i = 0; i < 4; i++) m1r[i] = m1[ty * 4 + i] * inv_temp;
    const float* m2base = mask2 + b * NN;

    float mrow[4], lrow[4], acc[4][4];
#pragma unroll
    for (int i = 0; i < 4; i++) {
        mrow[i] = -1e30f;
        lrow[i] = 0.f;
#pragma unroll
        for (int j = 0; j < 4; j++) acc[i][j] = 0.f;
    }

    for (int t = 0; t < NN / 64; t++) {
        const float* kb = kbase + t * 64 * 64;
        const float* vb = vbase + t * 64 * 64;
        __syncthreads();              // previous iter's smem reads done
#pragma unroll
        for (int i = 0; i < 4; i++) {
            int idx = tid + i * 256;
            int r   = idx >> 4;
            int c4  = (idx & 15) << 2;
            float4 f = *(const float4*)(kb + r * 64 + c4);
            Ks[(c4 + 0) * FPAD + r] = f.x;
            Ks[(c4 + 1) * FPAD + r] = f.y;
            Ks[(c4 + 2) * FPAD + r] = f.z;
            Ks[(c4 + 3) * FPAD + r] = f.w;
            float4 g = *(const float4*)(vb + r * 64 + c4);
            *(float4*)(Vs + r * FPAD + c4) = g;
        }
        __syncthreads();

        // ---- S = Q @ K^T (per-thread 4x4) ----
        float s[4][4];
#pragma unroll
        for (int i = 0; i < 4; i++)
#pragma unroll
            for (int j = 0; j < 4; j++) s[i][j] = 0.f;
#pragma unroll 8
        for (int kk = 0; kk < 64; kk++) {
            float a[4], bfr[4];
            *(float4*)a   = *(const float4*)(Qs + kk * FPAD + ty * 4);
            *(float4*)bfr = *(const float4*)(Ks + kk * FPAD + tx * 4);
#pragma unroll
            for (int i = 0; i < 4; i++)
#pragma unroll
                for (int j = 0; j < 4; j++) s[i][j] += a[i] * bfr[j];
        }

        // ---- scale + relative-confidence bias ----
        float m2c[4];
#pragma unroll
        for (int j = 0; j < 4; j++) m2c[j] = m2base[t * 64 + tx * 4 + j] * inv_temp;

        float tmax[4];
#pragma unroll
        for (int i = 0; i < 4; i++) {
            tmax[i] = -1e30f;
#pragma unroll
            for (int j = 0; j < 4; j++) {
                s[i][j] = s[i][j] * scale + m1r[i] - m2c[j];
                tmax[i] = fmaxf(tmax[i], s[i][j]);
            }
        }
        // row max over the 16 lanes (tx) that share each row
#pragma unroll
        for (int i = 0; i < 4; i++) {
#pragma unroll
            for (int off = 8; off >= 1; off >>= 1)
                tmax[i] = fmaxf(tmax[i], __shfl_xor_sync(0xffffffffu, tmax[i], off));
        }

        // ---- online softmax update ----
#pragma unroll
        for (int i = 0; i < 4; i++) {
            float mnew = fmaxf(mrow[i], tmax[i]);
            float corr = __expf(mrow[i] - mnew);
            mrow[i] = mnew;
            lrow[i] *= corr;
#pragma unroll
            for (int j = 0; j < 4; j++) acc[i][j] *= corr;
            float rsum = 0.f;
#pragma unroll
            for (int j = 0; j < 4; j++) {
                float p = __expf(s[i][j] - mnew);
                s[i][j] = p;
                rsum += p;
            }
#pragma unroll
            for (int off = 8; off >= 1; off >>= 1)
                rsum += __shfl_xor_sync(0xffffffffu, rsum, off);
            lrow[i] += rsum;
        }

        // ---- write P transposed: Ps[c][r] ----
#pragma unroll
        for (int j = 0; j < 4; j++)
#pragma unroll
            for (int i = 0; i < 4; i++)
                Ps[(tx * 4 + j) * FPAD + ty * 4 + i] = s[i][j];
        __syncthreads();

        // ---- O += P @ V ----
#pragma unroll 8
        for (int c = 0; c < 64; c++) {
            float a[4], bfr[4];
            *(float4*)a   = *(const float4*)(Ps + c * FPAD + ty * 4);
            *(float4*)bfr = *(const float4*)(Vs + c * FPAD + tx * 4);
#pragma unroll
            for (int i = 0; i < 4; i++)
#pragma unroll
                for (int j = 0; j < 4; j++) acc[i][j] += a[i] * bfr[j];
        }
    }

    // ---- normalize and store to [B,N,C] ----
    float* obase = g_ao + ((size_t)(b * NN + mt * 64)) * NC + h * ND;
#pragma unroll
    for (int i = 0; i < 4; i++) {
        float inv_l = 1.0f / lrow[i];
        float4 o;
        o.x = acc[i][0] * inv_l;
        o.y = acc[i][1] * inv_l;
        o.z = acc[i][2] * inv_l;
        o.w = acc[i][3] * inv_l;
        *(float4*)(obase + (size_t)(ty * 4 + i) * NC + tx * 4) = o;
    }
}

// ---------------------------------------------------------------------------
// Output projection GEMM: g_t = g_ao @ Wo^T + bo   (flat [8192,768] layout)
// ---------------------------------------------------------------------------
__global__ __launch_bounds__(256) void oproj_gemm(
    const float* __restrict__ Wo, const float* __restrict__ bo)
{
    const int n0 = blockIdx.x * 64;
    const int m0 = blockIdx.y * 64;
    const int tid = threadIdx.x;
    const int tx = tid & 15;
    const int ty = tid >> 4;

    __shared__ float As[16 * 68];
    __shared__ float Ws[16 * 68];

    float acc[4][4];
#pragma unroll
    for (int i = 0; i < 4; i++)
#pragma unroll
        for (int j = 0; j < 4; j++) acc[i][j] = 0.f;

    const int lrow = tid >> 2;
    const int lk4  = (tid & 3) << 2;

    const float* arow = g_ao + (size_t)(m0 + lrow) * NC + lk4;
    const float* wrow = Wo + (size_t)(n0 + lrow) * NC + lk4;

    for (int k0 = 0; k0 < NC; k0 += 16) {
        float4 fa = *(const float4*)(arow + k0);
        float4 fw = *(const float4*)(wrow + k0);
        __syncthreads();
        As[(lk4 + 0) * 68 + lrow] = fa.x;
        As[(lk4 + 1) * 68 + lrow] = fa.y;
        As[(lk4 + 2) * 68 + lrow] = fa.z;
        As[(lk4 + 3) * 68 + lrow] = fa.w;
        Ws[(lk4 + 0) * 68 + lrow] = fw.x;
        Ws[(lk4 + 1) * 68 + lrow] = fw.y;
        Ws[(lk4 + 2) * 68 + lrow] = fw.z;
        Ws[(lk4 + 3) * 68 + lrow] = fw.w;
        __syncthreads();
#pragma unroll
        for (int kk = 0; kk < 16; kk++) {
            float a[4], b[4];
            *(float4*)a = *(const float4*)(As + kk * 68 + ty * 4);
            *(float4*)b = *(const float4*)(Ws + kk * 68 + tx * 4);
#pragma unroll
            for (int i = 0; i < 4; i++)
#pragma unroll
                for (int j = 0; j < 4; j++) acc[i][j] += a[i] * b[j];
        }
    }

    float bb[4];
#pragma unroll
    for (int j = 0; j < 4; j++) bb[j] = bo[n0 + tx * 4 + j];
#pragma unroll
    for (int i = 0; i < 4; i++) {
        float4 o;
        o.x = acc[i][0] + bb[0];
        o.y = acc[i][1] + bb[1];
        o.z = acc[i][2] + bb[2];
        o.w = acc[i][3] + bb[3];
        *(float4*)(g_t + (size_t)(m0 + ty * 4 + i) * NC + n0 + tx * 4) = o;
    }
}

// ---------------------------------------------------------------------------
// LayerNorm(0.5*x1 + g_t) over last dim (768). One block per row.
// ---------------------------------------------------------------------------
__global__ __launch_bounds__(256) void ln_kernel(
    const float* __restrict__ x1, const float* __restrict__ gamma,
    const float* __restrict__ beta, float* __restrict__ out)
{
    const int row = blockIdx.x;
    const int tid = threadIdx.x;
    const float* tr = g_t + (size_t)row * NC;
    const float* xr = x1 + (size_t)row * NC;

    float z[3];
    float s = 0.f;
#pragma unroll
    for (int u = 0; u < 3; u++) {
        int idx = tid + u * 256;
        z[u] = 0.5f * xr[idx] + tr[idx];
        s += z[u];
    }

    __shared__ float red[8];
#pragma unroll
    for (int off = 16; off >= 1; off >>= 1) s += __shfl_xor_sync(0xffffffffu, s, off);
    if ((tid & 31) == 0) red[tid >> 5] = s;
    __syncthreads();
    float tot = 0.f;
#pragma unroll
    for (int w = 0; w < 8; w++) tot += red[w];
    const float mu = tot * (1.0f / NC);

    float s2 = 0.f;
#pragma unroll
    for (int u = 0; u < 3; u++) {
        float d = z[u] - mu;
        s2 += d * d;
    }
    __syncthreads();
#pragma unroll
    for (int off = 16; off >= 1; off >>= 1) s2 += __shfl_xor_sync(0xffffffffu, s2, off);
    if ((tid & 31) == 0) red[tid >> 5] = s2;
    __syncthreads();
    float tot2 = 0.f;
#pragma unroll
    for (int w = 0; w < 8; w++) tot2 += red[w];
    const float rstd = rsqrtf(tot2 * (1.0f / NC) + 1e-5f);

    float* orow = out + (size_t)row * NC;
#pragma unroll
    for (int u = 0; u < 3; u++) {
        int idx = tid + u * 256;
        orow[idx] = (z[u] - mu) * rstd * gamma[idx] + beta[idx];
    }
}

// ---------------------------------------------------------------------------
extern "C" void kernel_launch(void* const* d_in, const int* in_sizes, int n_in,
                              void* d_out, int out_size)
{
    (void)in_sizes; (void)n_in; (void)out_size;
    const float* x1    = (const float*)d_in[0];
    const float* x2    = (const float*)d_in[1];
    const float* mask1 = (const float*)d_in[2];
    const float* mask2 = (const float*)d_in[3];
    const float* Wq    = (const float*)d_in[4];
    const float* bq    = (const float*)d_in[5];
    const float* Wk    = (const float*)d_in[6];
    const float* bk    = (const float*)d_in[7];
    const float* Wv    = (const float*)d_in[8];
    const float* bv    = (const float*)d_in[9];
    const float* Wo    = (const float*)d_in[10];
    const float* bo    = (const float*)d_in[11];
    const float* temp  = (const float*)d_in[12];
    const float* gamma = (const float*)d_in[13];
    const float* beta  = (const float*)d_in[14];
    float* out = (float*)d_out;

    const int FLASH_SMEM = 4 * 64 * FPAD * (int)sizeof(float);  // 69632 B
    cudaFuncSetAttribute(flash_kernel,
                         cudaFuncAttributeMaxDynamicSharedMemorySize, FLASH_SMEM);

    qkv_gemm<<<dim3(NC / 64, (NB * NN) / 64, 3), 256>>>(x1, x2, Wq, bq, Wk, bk, Wv, bv);
    flash_kernel<<<dim3(NN / 64, NB * NH), 256, FLASH_SMEM>>>(mask1, mask2, temp);
    oproj_gemm<<<dim3(NC / 64, (NB * NN) / 64), 256>>>(Wo, bo);
    ln_kernel<<<NB * NN, 256>>>(x1, gamma, beta, out);
}